// round 15
// baseline (speedup 1.0000x reference)
#include <cuda_runtime.h>
#include <cstdint>
#include <cstddef>

// LSTM autoencoder, round 15 = R14 + decoder P1 diet: Whh0 moved to blocked
// smem; P4's idle helper half precomputes the Whh0@h0[s] partial of
// gates0[s+1] (hidden under act1); P1 shrinks to M@h1 + partial.
// Main: 128 CTAs x 256 threads; each CTA owns 2 batch elements.

#define Tn 1024

// smem float offsets (main kernel)
#define OFF_WA   0        // dec Whh1 blocked [16c][256g][4]
#define OFF_WB   16384    // dec Whh0 blocked [16c][256g][4]
#define OFF_XW   32768    // [2][512] XW double buffer
#define OFF_H0   33792    // [2 parity][2 batch][64]
#define OFF_H1   34048    // [2 parity][2 batch][64] (encoder uses parity 0)
#define OFF_G    34304    // [1024]: gates @0..512, partial/p / enc gates0 @512..1024
#define SMEM_FLOATS 35328 // 141312 bytes

__device__ __align__(16) float g_M[256 * 64];             // dec_Wih0 @ fcW
__device__ __align__(16) float g_XW[128u * 1024u * 512u]; // enc L0 x-part, bias folded
__device__ __align__(16) float g_H1[256u * 1024u * 64u];  // decoder h1 stream

__device__ __forceinline__ void fma2(unsigned long long& acc,
                                     unsigned long long a, unsigned long long b) {
    asm("fma.rn.f32x2 %0, %1, %2, %3;" : "=l"(acc) : "l"(a), "l"(b), "l"(acc));
}
__device__ __forceinline__ unsigned long long padd(unsigned long long a, unsigned long long b) {
    unsigned long long r;
    asm("add.rn.f32x2 %0, %1, %2;" : "=l"(r) : "l"(a), "l"(b));
    return r;
}
__device__ __forceinline__ float psum(unsigned long long v) {
    float lo, hi;
    asm("mov.b64 {%0, %1}, %2;" : "=f"(lo), "=f"(hi) : "l"(v));
    return lo + hi;
}
__device__ __forceinline__ float sigm_f(float v) {
    return __fdividef(1.f, 1.f + __expf(-v));
}
__device__ __forceinline__ float tanh_f(float v) {
    float a = fabsf(v);
    float e = __expf(-2.f * a);
    float r = __fdividef(1.f - e, 1.f + e);
    return v < 0.f ? -r : r;
}
__device__ __forceinline__ float cellact(float gi, float gf, float gg, float go, float& c) {
    c = sigm_f(gf) * c + sigm_f(gi) * tanh_f(gg);
    return sigm_f(go) * tanh_f(c);
}

__global__ void __launch_bounds__(128, 4)
prep_kernel(const float* __restrict__ dW0i, const float* __restrict__ fcW) {
    int id = blockIdx.x * blockDim.x + threadIdx.x;  // 0..16383
    int g = id >> 6, j = id & 63;
    float a0 = 0.f, a1 = 0.f;
    #pragma unroll 8
    for (int d = 0; d < 128; d += 2) {
        a0 = fmaf(dW0i[g * 128 + d],     fcW[d * 64 + j],       a0);
        a1 = fmaf(dW0i[g * 128 + d + 1], fcW[(d + 1) * 64 + j], a1);
    }
    g_M[id] = a0 + a1;
}

// XW[pair][s][e][g] = x[b,s,:] . Wih0[g,:] + eb0i[g] + eb0h[g]  (2-step ILP)
__global__ void __launch_bounds__(256, 1)
prep_x_kernel(const float* __restrict__ x, const float* __restrict__ eW0i,
              const float* __restrict__ eb0i, const float* __restrict__ eb0h) {
    __shared__ float sx[32 * 128];
    const int b  = blockIdx.x;     // 0..255
    const int ch = blockIdx.y;     // 0..31
    const int t  = threadIdx.x;    // gate 0..255

    for (int i = t; i < 32 * 128; i += 256)
        sx[i] = x[((size_t)b * Tn + ch * 32) * 128 + i];

    unsigned long long w[64];
    const ulonglong2* p = (const ulonglong2*)(eW0i + t * 128);
    #pragma unroll
    for (int i = 0; i < 32; i++) { ulonglong2 v = p[i]; w[2*i] = v.x; w[2*i+1] = v.y; }
    const float bias = eb0i[t] + eb0h[t];
    __syncthreads();

    float* obase = g_XW + (((size_t)(b >> 1) * Tn + ch * 32) * 2 + (b & 1)) * 256 + t;
    #pragma unroll 2
    for (int s = 0; s < 32; s += 2) {
        const ulonglong2* xp0 = (const ulonglong2*)(sx + s * 128);
        const ulonglong2* xp1 = (const ulonglong2*)(sx + (s + 1) * 128);
        unsigned long long q0 = 0ull, q1 = 0ull, r0 = 0ull, r1 = 0ull;
        #pragma unroll
        for (int i = 0; i < 32; i++) {
            ulonglong2 v0 = xp0[i]; ulonglong2 v1 = xp1[i];
            fma2(q0, w[2*i], v0.x); fma2(q1, w[2*i+1], v0.y);
            fma2(r0, w[2*i], v1.x); fma2(r1, w[2*i+1], v1.y);
        }
        obase[(size_t)s * 512]       = psum(padd(q0, q1)) + bias;
        obase[(size_t)(s + 1) * 512] = psum(padd(r0, r1)) + bias;
    }
}

// out[b][s][o] = h1[b][s] . fcW[o] + fcb[o]
// Register-tiled: thread owns 8 outputs (o = oi + 16k) x 4 steps (s = sg*4+j).
__global__ void __launch_bounds__(256, 2)
fc_kernel(const float* __restrict__ fcW, const float* __restrict__ fcb,
          float* __restrict__ out) {
    __shared__ float sh[64 * 64];     // 64-step h1 tile (16 KB)
    __shared__ float sw[16 * 512];    // fcW blocked [16c][128o][4] (32 KB)
    const int b  = blockIdx.x;        // 0..255
    const int ch = blockIdx.y;        // 0..15
    const int t  = threadIdx.x;
    const int oi = t & 15;            // output interleave base
    const int sg = t >> 4;            // step group 0..15

    for (int idx = t; idx < 128 * 64; idx += 256) {
        int o = idx >> 6, k = idx & 63;
        sw[(k >> 2) * 512 + o * 4 + (k & 3)] = fcW[idx];
    }
    {
        const float4* src = (const float4*)(g_H1 + ((size_t)b * Tn + ch * 64) * 64);
        float4* dst = (float4*)sh;
        #pragma unroll
        for (int i = 0; i < 4; i++) dst[t + i * 256] = src[t + i * 256];
    }
    __syncthreads();

    unsigned long long acc[8][4];
    #pragma unroll
    for (int k = 0; k < 8; k++)
        #pragma unroll
        for (int j = 0; j < 4; j++) acc[k][j] = 0ull;

    const ulonglong2* swp = (const ulonglong2*)sw;   // [c*128 + o]
    #pragma unroll 2
    for (int c = 0; c < 16; c++) {
        ulonglong2 hv[4];
        #pragma unroll
        for (int j = 0; j < 4; j++)
            hv[j] = ((const ulonglong2*)(sh + (sg * 4 + j) * 64))[c];
        ulonglong2 wv[8];
        #pragma unroll
        for (int k = 0; k < 8; k++)
            wv[k] = swp[c * 128 + oi + 16 * k];
        #pragma unroll
        for (int k = 0; k < 8; k++)
            #pragma unroll
            for (int j = 0; j < 4; j++) {
                fma2(acc[k][j], wv[k].x, hv[j].x);
                fma2(acc[k][j], wv[k].y, hv[j].y);
            }
    }

    float* obase = out + ((size_t)b * Tn + ch * 64) * 128;
    #pragma unroll
    for (int k = 0; k < 8; k++) {
        const int o = oi + 16 * k;
        const float bo = fcb[o];
        #pragma unroll
        for (int j = 0; j < 4; j++) {
            float r = psum(acc[k][j]) + bo;
            __stcg(obase + (size_t)(sg * 4 + j) * 128 + o, r);
        }
    }
}

__global__ void __launch_bounds__(256, 1)
lstm_ae_kernel(const float* __restrict__ x,
               const float* __restrict__ eW0i, const float* __restrict__ eW0h,
               const float* __restrict__ eb0i, const float* __restrict__ eb0h,
               const float* __restrict__ eW1i, const float* __restrict__ eW1h,
               const float* __restrict__ eb1i, const float* __restrict__ eb1h,
               const float* __restrict__ dW0i, const float* __restrict__ dW0h,
               const float* __restrict__ db0i, const float* __restrict__ db0h,
               const float* __restrict__ dW1i, const float* __restrict__ dW1h,
               const float* __restrict__ db1i, const float* __restrict__ db1h,
               const float* __restrict__ fcW,  const float* __restrict__ fcb,
               float* __restrict__ out)
{
    extern __shared__ float sm[];
    float* sWA = sm + OFF_WA;
    float* sWB = sm + OFF_WB;
    float* sXW = sm + OFF_XW;
    float* sH0 = sm + OFF_H0;
    float* sH1 = sm + OFF_H1;
    float* sG  = sm + OFF_G;

    const int t  = threadIdx.x;
    const int b0 = blockIdx.x * 2;
    const int aj = t & 63;
    const int ab = (t >> 6) & 1;

    float c0 = 0.f, c1 = 0.f;

    // ---- stage decoder Whh1 + Whh0 (blocked) up front ----
    for (int idx = t; idx < 256 * 64; idx += 256) {
        int g = idx >> 6, k = idx & 63;
        int off = (k >> 2) * 1024 + g * 4 + (k & 3);
        sWA[off] = dW1h[idx];
        sWB[off] = dW0h[idx];
    }
    if (t < 128) sH1[t] = 0.f;

    // ================= ENCODER (2 phases/step) =================
    {
        unsigned long long wH0[32], wI1[32], wH1[32];   // rows t of Whh0, Wih1, Whh1
        {
            const ulonglong2* p = (const ulonglong2*)(eW0h + t * 64);
            #pragma unroll
            for (int i = 0; i < 16; i++) { ulonglong2 v = p[i]; wH0[2*i] = v.x; wH0[2*i+1] = v.y; }
            const ulonglong2* q = (const ulonglong2*)(eW1i + t * 64);
            #pragma unroll
            for (int i = 0; i < 16; i++) { ulonglong2 v = q[i]; wI1[2*i] = v.x; wI1[2*i+1] = v.y; }
            const ulonglong2* r = (const ulonglong2*)(eW1h + t * 64);
            #pragma unroll
            for (int i = 0; i < 16; i++) { ulonglong2 v = r[i]; wH1[2*i] = v.x; wH1[2*i+1] = v.y; }
        }
        const float bias1 = eb1i[t] + eb1h[t];
        const size_t xwbase = (size_t)blockIdx.x * Tn * 512;

        // prologue: XW[0] -> slot0; gates0[0]; act0[0]; prefetch XW[1],XW[2]
        if (t < 128) {
            const float* src = g_XW + xwbase + t * 4;
            uint32_t dst = (uint32_t)__cvta_generic_to_shared(sXW + t * 4);
            asm volatile("cp.async.cg.shared.global [%0], [%1], 16;" :: "r"(dst), "l"(src) : "memory");
        }
        asm volatile("cp.async.commit_group;" ::: "memory");
        asm volatile("cp.async.wait_group 0;" ::: "memory");
        __syncthreads();

        sG[512 + t] = sXW[t];
        sG[768 + t] = sXW[256 + t];
        __syncthreads();

        if (t >= 128) {
            int t2 = t - 128, aB = (t2 >> 6) & 1, aj2 = t2 & 63;
            const float* gq = sG + 512 + aB * 256;
            sH0[aB * 64 + aj2] = cellact(gq[aj2], gq[64 + aj2], gq[128 + aj2], gq[192 + aj2], c0);
        } else {
            const float* src = g_XW + xwbase + (size_t)1 * 512 + t * 4;
            uint32_t dst = (uint32_t)__cvta_generic_to_shared(sXW + 512 + t * 4);
            asm volatile("cp.async.cg.shared.global [%0], [%1], 16;" :: "r"(dst), "l"(src) : "memory");
        }
        asm volatile("cp.async.commit_group;" ::: "memory");
        if (t < 128) {
            const float* src = g_XW + xwbase + (size_t)2 * 512 + t * 4;
            uint32_t dst = (uint32_t)__cvta_generic_to_shared(sXW + t * 4);
            asm volatile("cp.async.cg.shared.global [%0], [%1], 16;" :: "r"(dst), "l"(src) : "memory");
        }
        asm volatile("cp.async.commit_group;" ::: "memory");
        __syncthreads();

        for (int s = 0; s < Tn; s++) {
            asm volatile("cp.async.wait_group 1;" ::: "memory");
            {
                const float* xw = sXW + ((s + 1) & 1) * 512;
                const ulonglong2* h0a = (const ulonglong2*)(sH0);
                const ulonglong2* h0b = (const ulonglong2*)(sH0 + 64);
                const ulonglong2* h1a = (const ulonglong2*)(sH1);
                const ulonglong2* h1b = (const ulonglong2*)(sH1 + 64);
                unsigned long long qa0 = 0, qa1 = 0, qb0 = 0, qb1 = 0;   // Wih1@h0
                unsigned long long ra0 = 0, ra1 = 0, rb0 = 0, rb1 = 0;   // Whh1@h1
                unsigned long long sa0 = 0, sa1 = 0, sb0 = 0, sb1 = 0;   // Whh0@h0
                #pragma unroll
                for (int i = 0; i < 16; i++) {
                    ulonglong2 va = h0a[i], vb = h0b[i];
                    fma2(qa0, wI1[2*i], va.x); fma2(qa1, wI1[2*i+1], va.y);
                    fma2(qb0, wI1[2*i], vb.x); fma2(qb1, wI1[2*i+1], vb.y);
                    fma2(sa0, wH0[2*i], va.x); fma2(sa1, wH0[2*i+1], va.y);
                    fma2(sb0, wH0[2*i], vb.x); fma2(sb1, wH0[2*i+1], vb.y);
                    ulonglong2 wa = h1a[i], wb = h1b[i];
                    fma2(ra0, wH1[2*i], wa.x); fma2(ra1, wH1[2*i+1], wa.y);
                    fma2(rb0, wH1[2*i], wb.x); fma2(rb1, wH1[2*i+1], wb.y);
                }
                sG[t]       = psum(padd(padd(qa0, qa1), padd(ra0, ra1))) + bias1;
                sG[256 + t] = psum(padd(padd(qb0, qb1), padd(rb0, rb1))) + bias1;
                sG[512 + t] = xw[t]       + psum(padd(sa0, sa1));
                sG[768 + t] = xw[256 + t] + psum(padd(sb0, sb1));
            }
            __syncthreads();

            if (t < 128) {
                const float* gq = sG + ab * 256;
                sH1[ab * 64 + aj] = cellact(gq[aj], gq[64 + aj], gq[128 + aj], gq[192 + aj], c1);
            } else {
                if (s + 1 < Tn) {
                    int t2 = t - 128, aB = (t2 >> 6) & 1, aj2 = t2 & 63;
                    const float* gq = sG + 512 + aB * 256;
                    sH0[aB * 64 + aj2] = cellact(gq[aj2], gq[64 + aj2], gq[128 + aj2], gq[192 + aj2], c0);
                }
                if (s + 3 < Tn) {
                    int l = t - 128;
                    const float* src = g_XW + xwbase + (size_t)(s + 3) * 512 + l * 4;
                    uint32_t dst = (uint32_t)__cvta_generic_to_shared(sXW + ((s + 1) & 1) * 512 + l * 4);
                    asm volatile("cp.async.cg.shared.global [%0], [%1], 16;" :: "r"(dst), "l"(src) : "memory");
                }
            }
            asm volatile("cp.async.commit_group;" ::: "memory");
            __syncthreads();
        }
        asm volatile("cp.async.wait_group 0;" ::: "memory");
    }

    // ================= TRANSITION =================
    if (t >= 128) sG[t - 128] = c0;
    __syncthreads();
    if (t < 128) {
        c0 = tanh_f(sG[t]);
        c1 = tanh_f(c1);
        sH0[t] = tanh_f(sH0[t]);   // h0 init -> parity 0
        sH1[t] = tanh_f(sH1[t]);   // h1 init -> parity 0
    }
    unsigned long long wM[32];  // M row (over h1)
    unsigned long long wC[32];  // Wih1 row (over h0)
    {
        const ulonglong2* p = (const ulonglong2*)(g_M + t * 64);
        #pragma unroll
        for (int i = 0; i < 16; i++) { ulonglong2 v = p[i]; wM[2*i] = v.x; wM[2*i+1] = v.y; }
        const ulonglong2* r = (const ulonglong2*)(dW1i + t * 64);
        #pragma unroll
        for (int i = 0; i < 16; i++) { ulonglong2 v = r[i]; wC[2*i] = v.x; wC[2*i+1] = v.y; }
    }
    const float bias0 = db0i[t] + db0h[t];
    float b0fold;
    {
        float a = 0.f;
        #pragma unroll 4
        for (int d = 0; d < 128; d++) a = fmaf(dW0i[t * 128 + d], fcb[d], a);
        b0fold = bias0 + a;   // bias0 + Wih0 @ fcb
    }
    const float bias1 = db1i[t] + db1h[t];
    __syncthreads();

    // ================= DECODER =================
    const int u = t - 128;                            // helper id (t>=128)
    const ulonglong2* whp = (const ulonglong2*)sWA;   // Whh1 blocked [c*256 + g]
    const ulonglong2* whb = (const ulonglong2*)sWB;   // Whh0 blocked [c*256 + g]

    // prologue: helpers compute Whh0@h0_init partial for s=0 into sG[512..1024)
    if (t >= 128) {
        const ulonglong2* h0a = (const ulonglong2*)(sH0);
        const ulonglong2* h0b = (const ulonglong2*)(sH0 + 64);
        unsigned long long pA0 = 0, pA1 = 0, pB0 = 0, pB1 = 0;
        #pragma unroll
        for (int c = 0; c < 16; c++) {
            ulonglong2 w1 = whb[c * 256 + u];
            ulonglong2 w2 = whb[c * 256 + u + 128];
            ulonglong2 hA = h0a[c], hB = h0b[c];
            fma2(pA0, w1.x, hA.x); fma2(pA0, w1.y, hA.y);
            fma2(pA1, w1.x, hB.x); fma2(pA1, w1.y, hB.y);
            fma2(pB0, w2.x, hA.x); fma2(pB0, w2.y, hA.y);
            fma2(pB1, w2.x, hB.x); fma2(pB1, w2.y, hB.y);
        }
        sG[512 + u]       = psum(pA0);
        sG[768 + u]       = psum(pA1);
        sG[512 + u + 128] = psum(pB0);
        sG[768 + u + 128] = psum(pB1);
    }
    __syncthreads();

    for (int s = 0; s < Tn; s++) {
        const int par = s & 1;
        float*       h0w = sH0 + (par ^ 1) * 128;
        const float* h1r = sH1 + par * 128;
        float*       h1w = sH1 + (par ^ 1) * 128;

        // ---- P1: gates0 = partial(sG) (+ M@h1[s-1] if s>0) + bias ----
        {
            float pa = sG[512 + t], pb = sG[768 + t];
            float ga, gb;
            if (s > 0) {
                const ulonglong2* h1a = (const ulonglong2*)(h1r);
                const ulonglong2* h1b = (const ulonglong2*)(h1r + 64);
                unsigned long long a0 = 0, a1 = 0, c0q = 0, c1q = 0;
                #pragma unroll
                for (int i = 0; i < 16; i++) {
                    ulonglong2 ha = h1a[i]; ulonglong2 hb = h1b[i];
                    fma2(a0, wM[2*i], ha.x); fma2(a1, wM[2*i+1], ha.y);
                    fma2(c0q, wM[2*i], hb.x); fma2(c1q, wM[2*i+1], hb.y);
                }
                ga = psum(padd(a0, a1)) + pa + b0fold;
                gb = psum(padd(c0q, c1q)) + pb + b0fold;
            } else {
                ga = pa + bias0;
                gb = pb + bias0;
            }
            sG[t] = ga; sG[256 + t] = gb;
        }
        __syncthreads();

        // ---- P2: act0 (t<128) || p = Whh1@h1[s-1] for gates u,u+128 (t>=128) ----
        if (t < 128) {
            const float* gq = sG + ab * 256;
            h0w[ab * 64 + aj] = cellact(gq[aj], gq[64 + aj], gq[128 + aj], gq[192 + aj], c0);
        } else {
            const ulonglong2* h1a = (const ulonglong2*)(h1r);
            const ulonglong2* h1b = (const ulonglong2*)(h1r + 64);
            unsigned long long pA0 = 0, pA1 = 0, pB0 = 0, pB1 = 0;
            #pragma unroll
            for (int c = 0; c < 16; c++) {
                ulonglong2 w1 = whp[c * 256 + u];
                ulonglong2 w2 = whp[c * 256 + u + 128];
                ulonglong2 hA = h1a[c], hB = h1b[c];
                fma2(pA0, w1.x, hA.x); fma2(pA0, w1.y, hA.y);
                fma2(pA1, w1.x, hB.x); fma2(pA1, w1.y, hB.y);
                fma2(pB0, w2.x, hA.x); fma2(pB0, w2.y, hA.y);
                fma2(pB1, w2.x, hB.x); fma2(pB1, w2.y, hB.y);
            }
            sG[512 + u]       = psum(pA0);
            sG[768 + u]       = psum(pA1);
            sG[512 + u + 128] = psum(pB0);
            sG[768 + u + 128] = psum(pB1);
        }
        __syncthreads();

        // ---- P3: gates1 = Wih1@h0[s] (regs) + p + bias1 ----
        {
            const ulonglong2* h0a = (const ulonglong2*)(h0w);
            const ulonglong2* h0b = (const ulonglong2*)(h0w + 64);
            unsigned long long q00 = 0, q01 = 0, q10 = 0, q11 = 0;
            #pragma unroll
            for (int i = 0; i < 16; i++) {
                ulonglong2 va = h0a[i]; ulonglong2 vb = h0b[i];
                fma2(q00, wC[2*i], va.x); fma2(q01, wC[2*i+1], va.y);
                fma2(q10, wC[2*i], vb.x); fma2(q11, wC[2*i+1], vb.y);
            }
            sG[t]       = psum(padd(q00, q01)) + sG[512 + t] + bias1;
            sG[256 + t] = psum(padd(q10, q11)) + sG[768 + t] + bias1;
        }
        __syncthreads();

        // ---- P4: act1 + h1 stream (t<128) || Whh0@h0[s] partial for s+1 (t>=128) ----
        if (t < 128) {
            const float* gq = sG + ab * 256;
            float v = cellact(gq[aj], gq[64 + aj], gq[128 + aj], gq[192 + aj], c1);
            h1w[ab * 64 + aj] = v;
            g_H1[((size_t)(b0 + ab) * Tn + s) * 64 + aj] = v;
        } else {
            const ulonglong2* h0a = (const ulonglong2*)(h0w);
            const ulonglong2* h0b = (const ulonglong2*)(h0w + 64);
            unsigned long long pA0 = 0, pA1 = 0, pB0 = 0, pB1 = 0;
            #pragma unroll
            for (int c = 0; c < 16; c++) {
                ulonglong2 w1 = whb[c * 256 + u];
                ulonglong2 w2 = whb[c * 256 + u + 128];
                ulonglong2 hA = h0a[c], hB = h0b[c];
                fma2(pA0, w1.x, hA.x); fma2(pA0, w1.y, hA.y);
                fma2(pA1, w1.x, hB.x); fma2(pA1, w1.y, hB.y);
                fma2(pB0, w2.x, hA.x); fma2(pB0, w2.y, hA.y);
                fma2(pB1, w2.x, hB.x); fma2(pB1, w2.y, hB.y);
            }
            sG[512 + u]       = psum(pA0);
            sG[768 + u]       = psum(pA1);
            sG[512 + u + 128] = psum(pB0);
            sG[768 + u + 128] = psum(pB1);
        }
        __syncthreads();
    }
}

extern "C" void kernel_launch(void* const* d_in, const int* in_sizes, int n_in,
                              void* d_out, int out_size) {
    (void)in_sizes; (void)n_in; (void)out_size;
    const float* x    = (const float*)d_in[0];
    const float* eW0i = (const float*)d_in[1];
    const float* eW0h = (const float*)d_in[2];
    const float* eb0i = (const float*)d_in[3];
    const float* eb0h = (const float*)d_in[4];
    const float* eW1i = (const float*)d_in[5];
    const float* eW1h = (const float*)d_in[6];
    const float* eb1i = (const float*)d_in[7];
    const float* eb1h = (const float*)d_in[8];
    const float* dW0i = (const float*)d_in[9];
    const float* dW0h = (const float*)d_in[10];
    const float* db0i = (const float*)d_in[11];
    const float* db0h = (const float*)d_in[12];
    const float* dW1i = (const float*)d_in[13];
    const float* dW1h = (const float*)d_in[14];
    const float* db1i = (const float*)d_in[15];
    const float* db1h = (const float*)d_in[16];
    const float* fcW  = (const float*)d_in[17];
    const float* fcb  = (const float*)d_in[18];

    prep_kernel<<<128, 128>>>(dW0i, fcW);
    dim3 pgrid(256, 32);
    prep_x_kernel<<<pgrid, 256>>>(x, eW0i, eb0i, eb0h);

    cudaFuncSetAttribute(lstm_ae_kernel, cudaFuncAttributeMaxDynamicSharedMemorySize,
                         SMEM_FLOATS * (int)sizeof(float));
    lstm_ae_kernel<<<128, 256, SMEM_FLOATS * sizeof(float)>>>(
        x, eW0i, eW0h, eb0i, eb0h, eW1i, eW1h, eb1i, eb1h,
        dW0i, dW0h, db0i, db0h, dW1i, dW1h, db1i, db1h,
        fcW, fcb, (float*)d_out);

    dim3 fgrid(256, 16);
    fc_kernel<<<fgrid, 256>>>(fcW, fcb, (float*)d_out);
}

// round 16
// speedup vs baseline: 1.7720x; 1.7720x over previous
#include <cuda_runtime.h>
#include <cstdint>
#include <cstddef>

// LSTM autoencoder, round 16 = R14 main kernel + R14 fc (both verbatim, best
// known) + register-tiled prep_x (same recipe that fixed fc in R14):
// thread owns 8 gates x 4 rows, 12 LDS per 64 fma2, blocked smem weights.
// Main: 128 CTAs x 256 threads; each CTA owns 2 batch elements.

#define Tn 1024

// smem float offsets (main kernel) — R14 layout
#define OFF_WA   0        // dec Whh1 blocked [16c][256g][4]
#define OFF_XW   24704    // [2][512] XW double buffer
#define OFF_H0   25728    // [2 parity][2 batch][64]
#define OFF_H1   25984    // [2 parity][2 batch][64] (encoder uses parity 0)
#define OFF_G    26240    // [1024]: gates @0..512, p / enc gates0 @512..1024
#define SMEM_FLOATS 27264 // 109056 bytes

__device__ __align__(16) float g_M[256 * 64];             // dec_Wih0 @ fcW
__device__ __align__(16) float g_XW[128u * 1024u * 512u]; // enc L0 x-part, bias folded
__device__ __align__(16) float g_H1[256u * 1024u * 64u];  // decoder h1 stream

__device__ __forceinline__ void fma2(unsigned long long& acc,
                                     unsigned long long a, unsigned long long b) {
    asm("fma.rn.f32x2 %0, %1, %2, %3;" : "=l"(acc) : "l"(a), "l"(b), "l"(acc));
}
__device__ __forceinline__ unsigned long long padd(unsigned long long a, unsigned long long b) {
    unsigned long long r;
    asm("add.rn.f32x2 %0, %1, %2;" : "=l"(r) : "l"(a), "l"(b));
    return r;
}
__device__ __forceinline__ float psum(unsigned long long v) {
    float lo, hi;
    asm("mov.b64 {%0, %1}, %2;" : "=f"(lo), "=f"(hi) : "l"(v));
    return lo + hi;
}
__device__ __forceinline__ float sigm_f(float v) {
    return __fdividef(1.f, 1.f + __expf(-v));
}
__device__ __forceinline__ float tanh_f(float v) {
    float a = fabsf(v);
    float e = __expf(-2.f * a);
    float r = __fdividef(1.f - e, 1.f + e);
    return v < 0.f ? -r : r;
}
__device__ __forceinline__ float cellact(float gi, float gf, float gg, float go, float& c) {
    c = sigm_f(gf) * c + sigm_f(gi) * tanh_f(gg);
    return sigm_f(go) * tanh_f(c);
}

__global__ void __launch_bounds__(128, 4)
prep_kernel(const float* __restrict__ dW0i, const float* __restrict__ fcW) {
    int id = blockIdx.x * blockDim.x + threadIdx.x;  // 0..16383
    int g = id >> 6, j = id & 63;
    float a0 = 0.f, a1 = 0.f;
    #pragma unroll 8
    for (int d = 0; d < 128; d += 2) {
        a0 = fmaf(dW0i[g * 128 + d],     fcW[d * 64 + j],       a0);
        a1 = fmaf(dW0i[g * 128 + d + 1], fcW[(d + 1) * 64 + j], a1);
    }
    g_M[id] = a0 + a1;
}

// XW[pair][s][e][g] = x[b,s,:] . Wih0[g,:] + eb0i[g] + eb0h[g]
// Register-tiled: block = (pair, 64-row chunk, gate-half of 128).
// Thread owns 8 gates (go = oi + 16k) x 4 rows (row = sg*4+j).
__global__ void __launch_bounds__(256, 1)
prep_x_kernel(const float* __restrict__ x, const float* __restrict__ eW0i,
              const float* __restrict__ eb0i, const float* __restrict__ eb0h) {
    __shared__ float sx[64 * 128];    // 64 rows (s,e) x 128 dims  (32 KB)
    __shared__ float sw[32 * 512];    // Wih0 half blocked [32c][128go][4] (64 KB)
    __shared__ float sbias[128];
    const int pair = blockIdx.x;      // 0..127
    const int rc   = blockIdx.y;      // 0..31 (64-row chunk)
    const int gh   = blockIdx.z;      // 0..1 (gate half)
    const int t    = threadIdx.x;
    const int oi   = t & 15;
    const int sg   = t >> 4;          // 0..15

    // stage weights blocked: chunk c (4 k's) of gate go at c*512 + go*4
    for (int idx = t; idx < 128 * 128; idx += 256) {
        int go = idx >> 7, k = idx & 127;
        sw[(k >> 2) * 512 + go * 4 + (k & 3)] = eW0i[(gh * 128 + go) * 128 + k];
    }
    if (t < 128) sbias[t] = eb0i[gh * 128 + t] + eb0h[gh * 128 + t];
    // stage x rows: row r -> (s = (rc*64+r)>>1, e = (rc*64+r)&1)
    for (int idx = t; idx < 64 * 128 / 4; idx += 256) {
        int r = idx >> 5, c4 = idx & 31;          // 32 float4 per row
        int grow = rc * 64 + r;
        const float4* src = (const float4*)(x + ((size_t)(pair * 2 + (grow & 1)) * Tn + (grow >> 1)) * 128);
        ((float4*)(sx + r * 128))[c4] = src[c4];
    }
    __syncthreads();

    unsigned long long acc[8][4];
    #pragma unroll
    for (int k = 0; k < 8; k++)
        #pragma unroll
        for (int j = 0; j < 4; j++) acc[k][j] = 0ull;

    const ulonglong2* swp = (const ulonglong2*)sw;   // [c*128 + go]
    #pragma unroll 2
    for (int c = 0; c < 32; c++) {
        ulonglong2 hv[4];
        #pragma unroll
        for (int j = 0; j < 4; j++)
            hv[j] = ((const ulonglong2*)(sx + (sg * 4 + j) * 128))[c];
        ulonglong2 wv[8];
        #pragma unroll
        for (int k = 0; k < 8; k++)
            wv[k] = swp[c * 128 + oi + 16 * k];
        #pragma unroll
        for (int k = 0; k < 8; k++)
            #pragma unroll
            for (int j = 0; j < 4; j++) {
                fma2(acc[k][j], wv[k].x, hv[j].x);
                fma2(acc[k][j], wv[k].y, hv[j].y);
            }
    }

    // store: XW[pair][s][e][g] with rows contiguous as (s*2+e)*256
    float* obase = g_XW + ((size_t)pair * Tn * 2 + (size_t)rc * 64) * 256 + gh * 128;
    #pragma unroll
    for (int k = 0; k < 8; k++) {
        const int go = oi + 16 * k;
        const float bo = sbias[go];
        #pragma unroll
        for (int j = 0; j < 4; j++) {
            float r = psum(acc[k][j]) + bo;
            __stcg(obase + (size_t)(sg * 4 + j) * 256 + go, r);
        }
    }
}

// out[b][s][o] = h1[b][s] . fcW[o] + fcb[o]  (R14-verbatim)
__global__ void __launch_bounds__(256, 2)
fc_kernel(const float* __restrict__ fcW, const float* __restrict__ fcb,
          float* __restrict__ out) {
    __shared__ float sh[64 * 64];
    __shared__ float sw[16 * 512];
    const int b  = blockIdx.x;
    const int ch = blockIdx.y;
    const int t  = threadIdx.x;
    const int oi = t & 15;
    const int sg = t >> 4;

    for (int idx = t; idx < 128 * 64; idx += 256) {
        int o = idx >> 6, k = idx & 63;
        sw[(k >> 2) * 512 + o * 4 + (k & 3)] = fcW[idx];
    }
    {
        const float4* src = (const float4*)(g_H1 + ((size_t)b * Tn + ch * 64) * 64);
        float4* dst = (float4*)sh;
        #pragma unroll
        for (int i = 0; i < 4; i++) dst[t + i * 256] = src[t + i * 256];
    }
    __syncthreads();

    unsigned long long acc[8][4];
    #pragma unroll
    for (int k = 0; k < 8; k++)
        #pragma unroll
        for (int j = 0; j < 4; j++) acc[k][j] = 0ull;

    const ulonglong2* swp = (const ulonglong2*)sw;
    #pragma unroll 2
    for (int c = 0; c < 16; c++) {
        ulonglong2 hv[4];
        #pragma unroll
        for (int j = 0; j < 4; j++)
            hv[j] = ((const ulonglong2*)(sh + (sg * 4 + j) * 64))[c];
        ulonglong2 wv[8];
        #pragma unroll
        for (int k = 0; k < 8; k++)
            wv[k] = swp[c * 128 + oi + 16 * k];
        #pragma unroll
        for (int k = 0; k < 8; k++)
            #pragma unroll
            for (int j = 0; j < 4; j++) {
                fma2(acc[k][j], wv[k].x, hv[j].x);
                fma2(acc[k][j], wv[k].y, hv[j].y);
            }
    }

    float* obase = out + ((size_t)b * Tn + ch * 64) * 128;
    #pragma unroll
    for (int k = 0; k < 8; k++) {
        const int o = oi + 16 * k;
        const float bo = fcb[o];
        #pragma unroll
        for (int j = 0; j < 4; j++) {
            float r = psum(acc[k][j]) + bo;
            __stcg(obase + (size_t)(sg * 4 + j) * 128 + o, r);
        }
    }
}

__global__ void __launch_bounds__(256, 1)
lstm_ae_kernel(const float* __restrict__ x,
               const float* __restrict__ eW0i, const float* __restrict__ eW0h,
               const float* __restrict__ eb0i, const float* __restrict__ eb0h,
               const float* __restrict__ eW1i, const float* __restrict__ eW1h,
               const float* __restrict__ eb1i, const float* __restrict__ eb1h,
               const float* __restrict__ dW0i, const float* __restrict__ dW0h,
               const float* __restrict__ db0i, const float* __restrict__ db0h,
               const float* __restrict__ dW1i, const float* __restrict__ dW1h,
               const float* __restrict__ db1i, const float* __restrict__ db1h,
               const float* __restrict__ fcW,  const float* __restrict__ fcb,
               float* __restrict__ out)
{
    extern __shared__ float sm[];
    float* sWA = sm + OFF_WA;
    float* sXW = sm + OFF_XW;
    float* sH0 = sm + OFF_H0;
    float* sH1 = sm + OFF_H1;
    float* sG  = sm + OFF_G;

    const int t  = threadIdx.x;
    const int b0 = blockIdx.x * 2;
    const int aj = t & 63;
    const int ab = (t >> 6) & 1;

    float c0 = 0.f, c1 = 0.f;

    // ---- stage decoder Whh1 (blocked) up front ----
    for (int idx = t; idx < 256 * 64; idx += 256) {
        int g = idx >> 6, k = idx & 63;
        sWA[(k >> 2) * 1024 + g * 4 + (k & 3)] = dW1h[idx];
    }
    if (t < 128) sH1[t] = 0.f;

    // ================= ENCODER (2 phases/step) =================
    {
        unsigned long long wH0[32], wI1[32], wH1[32];   // rows t of Whh0, Wih1, Whh1
        {
            const ulonglong2* p = (const ulonglong2*)(eW0h + t * 64);
            #pragma unroll
            for (int i = 0; i < 16; i++) { ulonglong2 v = p[i]; wH0[2*i] = v.x; wH0[2*i+1] = v.y; }
            const ulonglong2* q = (const ulonglong2*)(eW1i + t * 64);
            #pragma unroll
            for (int i = 0; i < 16; i++) { ulonglong2 v = q[i]; wI1[2*i] = v.x; wI1[2*i+1] = v.y; }
            const ulonglong2* r = (const ulonglong2*)(eW1h + t * 64);
            #pragma unroll
            for (int i = 0; i < 16; i++) { ulonglong2 v = r[i]; wH1[2*i] = v.x; wH1[2*i+1] = v.y; }
        }
        const float bias1 = eb1i[t] + eb1h[t];
        const size_t xwbase = (size_t)blockIdx.x * Tn * 512;

        // prologue: XW[0] -> slot0; gates0[0]; act0[0]; prefetch XW[1],XW[2]
        if (t < 128) {
            const float* src = g_XW + xwbase + t * 4;
            uint32_t dst = (uint32_t)__cvta_generic_to_shared(sXW + t * 4);
            asm volatile("cp.async.cg.shared.global [%0], [%1], 16;" :: "r"(dst), "l"(src) : "memory");
        }
        asm volatile("cp.async.commit_group;" ::: "memory");
        asm volatile("cp.async.wait_group 0;" ::: "memory");
        __syncthreads();

        sG[512 + t] = sXW[t];
        sG[768 + t] = sXW[256 + t];
        __syncthreads();

        if (t >= 128) {
            int t2 = t - 128, aB = (t2 >> 6) & 1, aj2 = t2 & 63;
            const float* gq = sG + 512 + aB * 256;
            sH0[aB * 64 + aj2] = cellact(gq[aj2], gq[64 + aj2], gq[128 + aj2], gq[192 + aj2], c0);
        } else {
            const float* src = g_XW + xwbase + (size_t)1 * 512 + t * 4;
            uint32_t dst = (uint32_t)__cvta_generic_to_shared(sXW + 512 + t * 4);
            asm volatile("cp.async.cg.shared.global [%0], [%1], 16;" :: "r"(dst), "l"(src) : "memory");
        }
        asm volatile("cp.async.commit_group;" ::: "memory");
        if (t < 128) {
            const float* src = g_XW + xwbase + (size_t)2 * 512 + t * 4;
            uint32_t dst = (uint32_t)__cvta_generic_to_shared(sXW + t * 4);
            asm volatile("cp.async.cg.shared.global [%0], [%1], 16;" :: "r"(dst), "l"(src) : "memory");
        }
        asm volatile("cp.async.commit_group;" ::: "memory");
        __syncthreads();

        for (int s = 0; s < Tn; s++) {
            asm volatile("cp.async.wait_group 1;" ::: "memory");
            {
                const float* xw = sXW + ((s + 1) & 1) * 512;
                const ulonglong2* h0a = (const ulonglong2*)(sH0);
                const ulonglong2* h0b = (const ulonglong2*)(sH0 + 64);
                const ulonglong2* h1a = (const ulonglong2*)(sH1);
                const ulonglong2* h1b = (const ulonglong2*)(sH1 + 64);
                unsigned long long qa0 = 0, qa1 = 0, qb0 = 0, qb1 = 0;   // Wih1@h0
                unsigned long long ra0 = 0, ra1 = 0, rb0 = 0, rb1 = 0;   // Whh1@h1
                unsigned long long sa0 = 0, sa1 = 0, sb0 = 0, sb1 = 0;   // Whh0@h0
                #pragma unroll
                for (int i = 0; i < 16; i++) {
                    ulonglong2 va = h0a[i], vb = h0b[i];
                    fma2(qa0, wI1[2*i], va.x); fma2(qa1, wI1[2*i+1], va.y);
                    fma2(qb0, wI1[2*i], vb.x); fma2(qb1, wI1[2*i+1], vb.y);
                    fma2(sa0, wH0[2*i], va.x); fma2(sa1, wH0[2*i+1], va.y);
                    fma2(sb0, wH0[2*i], vb.x); fma2(sb1, wH0[2*i+1], vb.y);
                    ulonglong2 wa = h1a[i], wb = h1b[i];
                    fma2(ra0, wH1[2*i], wa.x); fma2(ra1, wH1[2*i+1], wa.y);
                    fma2(rb0, wH1[2*i], wb.x); fma2(rb1, wH1[2*i+1], wb.y);
                }
                sG[t]       = psum(padd(padd(qa0, qa1), padd(ra0, ra1))) + bias1;
                sG[256 + t] = psum(padd(padd(qb0, qb1), padd(rb0, rb1))) + bias1;
                sG[512 + t] = xw[t]       + psum(padd(sa0, sa1));
                sG[768 + t] = xw[256 + t] + psum(padd(sb0, sb1));
            }
            __syncthreads();

            if (t < 128) {
                const float* gq = sG + ab * 256;
                sH1[ab * 64 + aj] = cellact(gq[aj], gq[64 + aj], gq[128 + aj], gq[192 + aj], c1);
            } else {
                if (s + 1 < Tn) {
                    int t2 = t - 128, aB = (t2 >> 6) & 1, aj2 = t2 & 63;
                    const float* gq = sG + 512 + aB * 256;
                    sH0[aB * 64 + aj2] = cellact(gq[aj2], gq[64 + aj2], gq[128 + aj2], gq[192 + aj2], c0);
                }
                if (s + 3 < Tn) {
                    int l = t - 128;
                    const float* src = g_XW + xwbase + (size_t)(s + 3) * 512 + l * 4;
                    uint32_t dst = (uint32_t)__cvta_generic_to_shared(sXW + ((s + 1) & 1) * 512 + l * 4);
                    asm volatile("cp.async.cg.shared.global [%0], [%1], 16;" :: "r"(dst), "l"(src) : "memory");
                }
            }
            asm volatile("cp.async.commit_group;" ::: "memory");
            __syncthreads();
        }
        asm volatile("cp.async.wait_group 0;" ::: "memory");
    }

    // ================= TRANSITION =================
    if (t >= 128) sG[t - 128] = c0;
    __syncthreads();
    if (t < 128) {
        c0 = tanh_f(sG[t]);
        c1 = tanh_f(c1);
        sH0[t] = tanh_f(sH0[t]);   // h0 init -> parity 0
        sH1[t] = tanh_f(sH1[t]);   // h1 init -> parity 0
    }
    unsigned long long wA[64];  // [0..31] M row (over h1), [32..63] Whh0 row (over h0)
    unsigned long long wC[32];  // Wih1 row (over h0)
    {
        const ulonglong2* p = (const ulonglong2*)(g_M + t * 64);
        #pragma unroll
        for (int i = 0; i < 16; i++) { ulonglong2 v = p[i]; wA[2*i] = v.x; wA[2*i+1] = v.y; }
        const ulonglong2* q = (const ulonglong2*)(dW0h + t * 64);
        #pragma unroll
        for (int i = 0; i < 16; i++) { ulonglong2 v = q[i]; wA[32+2*i] = v.x; wA[33+2*i] = v.y; }
        const ulonglong2* r = (const ulonglong2*)(dW1i + t * 64);
        #pragma unroll
        for (int i = 0; i < 16; i++) { ulonglong2 v = r[i]; wC[2*i] = v.x; wC[2*i+1] = v.y; }
    }
    const float bias0 = db0i[t] + db0h[t];
    float b0fold;
    {
        float a = 0.f;
        #pragma unroll 4
        for (int d = 0; d < 128; d++) a = fmaf(dW0i[t * 128 + d], fcb[d], a);
        b0fold = bias0 + a;   // bias0 + Wih0 @ fcb
    }
    const float bias1 = db1i[t] + db1h[t];
    __syncthreads();

    // ================= DECODER (R14-verbatim) =================
    const int u = t - 128;                            // helper id (t>=128)
    const ulonglong2* whp = (const ulonglong2*)sWA;   // Whh1 blocked [c*256 + g]

    for (int s = 0; s < Tn; s++) {
        const int par = s & 1;
        const float* h0r = sH0 + par * 128;
        float*       h0w = sH0 + (par ^ 1) * 128;
        const float* h1r = sH1 + par * 128;
        float*       h1w = sH1 + (par ^ 1) * 128;

        // ---- P1: gates0 = Whh0@h0[s-1] (+ M@h1[s-1] if s>0) ----
        {
            const ulonglong2* h0a = (const ulonglong2*)(h0r);
            const ulonglong2* h0b = (const ulonglong2*)(h0r + 64);
            const ulonglong2* h1a = (const ulonglong2*)(h1r);
            const ulonglong2* h1b = (const ulonglong2*)(h1r + 64);
            unsigned long long a0 = 0, a1 = 0, c0q = 0, c1q = 0;
            #pragma unroll
            for (int i = 0; i < 16; i++) {
                ulonglong2 va = h0a[i]; ulonglong2 vb = h0b[i];
                fma2(a0, wA[32 + 2*i], va.x); fma2(a1, wA[33 + 2*i], va.y);
                fma2(c0q, wA[32 + 2*i], vb.x); fma2(c1q, wA[33 + 2*i], vb.y);
                if (s > 0) {
                    ulonglong2 ha = h1a[i]; ulonglong2 hb = h1b[i];
                    fma2(a0, wA[2*i], ha.x); fma2(a1, wA[2*i+1], ha.y);
                    fma2(c0q, wA[2*i], hb.x); fma2(c1q, wA[2*i+1], hb.y);
                }
            }
            const float bb = (s > 0) ? b0fold : bias0;
            sG[t]       = psum(padd(a0, a1)) + bb;
            sG[256 + t] = psum(padd(c0q, c1q)) + bb;
        }
        __syncthreads();

        // ---- P2: act0 (t<128) || p = Whh1@h1[s-1] for gates u,u+128 (t>=128) ----
        if (t < 128) {
            const float* gq = sG + ab * 256;
            h0w[ab * 64 + aj] = cellact(gq[aj], gq[64 + aj], gq[128 + aj], gq[192 + aj], c0);
        } else {
            const ulonglong2* h1a = (const ulonglong2*)(h1r);
            const ulonglong2* h1b = (const ulonglong2*)(h1r + 64);
            unsigned long long pA0 = 0, pA1 = 0, pB0 = 0, pB1 = 0;
            #pragma unroll
            for (int c = 0; c < 16; c++) {
                ulonglong2 w1 = whp[c * 256 + u];
                ulonglong2 w2 = whp[c * 256 + u + 128];
                ulonglong2 hA = h1a[c], hB = h1b[c];
                fma2(pA0, w1.x, hA.x); fma2(pA0, w1.y, hA.y);
                fma2(pA1, w1.x, hB.x); fma2(pA1, w1.y, hB.y);
                fma2(pB0, w2.x, hA.x); fma2(pB0, w2.y, hA.y);
                fma2(pB1, w2.x, hB.x); fma2(pB1, w2.y, hB.y);
            }
            sG[512 + u]       = psum(pA0);
            sG[768 + u]       = psum(pA1);
            sG[512 + u + 128] = psum(pB0);
            sG[768 + u + 128] = psum(pB1);
        }
        __syncthreads();

        // ---- P3: gates1 = Wih1@h0[s] (regs) + p + bias1 ----
        {
            const ulonglong2* h0a = (const ulonglong2*)(h0w);
            const ulonglong2* h0b = (const ulonglong2*)(h0w + 64);
            unsigned long long q00 = 0, q01 = 0, q10 = 0, q11 = 0;
            #pragma unroll
            for (int i = 0; i < 16; i++) {
                ulonglong2 va = h0a[i]; ulonglong2 vb = h0b[i];
                fma2(q00, wC[2*i], va.x); fma2(q01, wC[2*i+1], va.y);
                fma2(q10, wC[2*i], vb.x); fma2(q11, wC[2*i+1], vb.y);
            }
            sG[t]       = psum(padd(q00, q01)) + sG[512 + t] + bias1;
            sG[256 + t] = psum(padd(q10, q11)) + sG[768 + t] + bias1;
        }
        __syncthreads();

        // ---- P4: act1 (t<128) + stream h1 to gmem ----
        if (t < 128) {
            const float* gq = sG + ab * 256;
            float v = cellact(gq[aj], gq[64 + aj], gq[128 + aj], gq[192 + aj], c1);
            h1w[ab * 64 + aj] = v;
            g_H1[((size_t)(b0 + ab) * Tn + s) * 64 + aj] = v;
        }
        __syncthreads();
    }
}

extern "C" void kernel_launch(void* const* d_in, const int* in_sizes, int n_in,
                              void* d_out, int out_size) {
    (void)in_sizes; (void)n_in; (void)out_size;
    const float* x    = (const float*)d_in[0];
    const float* eW0i = (const float*)d_in[1];
    const float* eW0h = (const float*)d_in[2];
    const float* eb0i = (const float*)d_in[3];
    const float* eb0h = (const float*)d_in[4];
    const float* eW1i = (const float*)d_in[5];
    const float* eW1h = (const float*)d_in[6];
    const float* eb1i = (const float*)d_in[7];
    const float* eb1h = (const float*)d_in[8];
    const float* dW0i = (const float*)d_in[9];
    const float* dW0h = (const float*)d_in[10];
    const float* db0i = (const float*)d_in[11];
    const float* db0h = (const float*)d_in[12];
    const float* dW1i = (const float*)d_in[13];
    const float* dW1h = (const float*)d_in[14];
    const float* db1i = (const float*)d_in[15];
    const float* db1h = (const float*)d_in[16];
    const float* fcW  = (const float*)d_in[17];
    const float* fcb  = (const float*)d_in[18];

    prep_kernel<<<128, 128>>>(dW0i, fcW);
    dim3 pgrid(128, 32, 2);
    prep_x_kernel<<<pgrid, 256>>>(x, eW0i, eb0i, eb0h);

    cudaFuncSetAttribute(lstm_ae_kernel, cudaFuncAttributeMaxDynamicSharedMemorySize,
                         SMEM_FLOATS * (int)sizeof(float));
    lstm_ae_kernel<<<128, 256, SMEM_FLOATS * sizeof(float)>>>(
        x, eW0i, eW0h, eb0i, eb0h, eW1i, eW1h, eb1i, eb1h,
        dW0i, dW0h, db0i, db0h, dW1i, dW1h, db1i, db1h,
        fcW, fcb, (float*)d_out);

    dim3 fgrid(256, 16);
    fc_kernel<<<fgrid, 256>>>(fcW, fcb, (float*)d_out);
}